// round 5
// baseline (speedup 1.0000x reference)
#include <cuda_runtime.h>
#include <stdint.h>

// carry_save_adder: exact-binary reduction.
// S_b = sum over kept i of value(x[b,i,:]); out bits = S_b & 0xFFFF, carry = S_b >> 16.
// Persistent grid at max occupancy (8 CTAs/SM x 256 thr = 2048 thr/SM, regs<=32).
// One warp per row; FFMA-imm nibble accumulation with the loop-invariant weight
// 2^((lane&3)*4) factored out; exact fp32 (S < 2^22); 5-shuffle warp reduce.

__global__ void __launch_bounds__(256, 8)
csa_kernel(const float4* __restrict__ x, const int* __restrict__ mask,
           float* __restrict__ out, int B)
{
    const unsigned FULL = 0xFFFFFFFFu;
    const int lane = threadIdx.x & 31;
    const int w0   = (blockIdx.x << 3) + (threadIdx.x >> 5);  // global warp id
    const int nw   = gridDim.x << 3;                          // total warps

    // Keep mask over the 64 values (indices 0,1 always kept).
    const unsigned mb_lo = __ballot_sync(FULL, mask[lane]      > 0) | 3u;
    const unsigned mb_hi = __ballot_sync(FULL, mask[lane + 32] > 0);

    // Chunk t handled by this lane holds value index i = 8t + (lane>>2);
    // its keep weight as a float multiplier:
    const unsigned q = (unsigned)lane >> 2;
    float keepf[8];
    #pragma unroll
    for (int t = 0; t < 8; ++t) {
        unsigned bit = (t < 4) ? ((mb_lo >> (8 * t + q)) & 1u)
                               : ((mb_hi >> (8 * (t - 4) + q)) & 1u);
        keepf[t] = bit ? 1.0f : 0.0f;
    }
    // Loop-invariant nibble weight 2^((lane&3)*4).
    const float wgt = __int_as_float((127 + (((int)lane & 3) << 2)) << 23);

    for (int row = w0; row < B; row += nw) {
        const float4* r = x + (size_t)row * 256;

        float sumf = 0.0f;
        #pragma unroll
        for (int t = 0; t < 8; ++t) {
            float4 v = r[lane + (t << 5)];
            float part = v.x;
            part = fmaf(v.y, 2.0f, part);
            part = fmaf(v.z, 4.0f, part);
            part = fmaf(v.w, 8.0f, part);
            sumf = fmaf(part, keepf[t], sumf);
        }
        sumf *= wgt;

        // Warp reduction (exact: integer-valued floats, total < 2^22).
        #pragma unroll
        for (int off = 16; off; off >>= 1)
            sumf += __shfl_xor_sync(FULL, sumf, off);

        const unsigned s = (unsigned)sumf;
        if (lane < 16)
            out[(size_t)row * 16 + lane] = (float)((s >> lane) & 1u);
        else if (lane == 16)
            out[(size_t)B * 16 + row] = (float)(s >> 16);
    }
}

extern "C" void kernel_launch(void* const* d_in, const int* in_sizes, int n_in,
                              void* d_out, int out_size)
{
    const float4* x   = (const float4*)d_in[0];   // (B, 64, 16) float32
    const int*    msk = (const int*)d_in[1];      // (64,) int32
    float*        out = (float*)d_out;            // B*16 output bits, then B carries

    int B = in_sizes[0] / 1024;                   // 64*16 floats per batch row

    // Persistent single wave: 8 CTAs/SM on 152 SMs = full 2048 threads/SM.
    int grid = 152 * 8;
    int maxg = (B + 7) / 8;
    if (grid > maxg) grid = maxg;
    csa_kernel<<<grid, 256>>>(x, msk, out, B);
}

// round 6
// speedup vs baseline: 1.0906x; 1.0906x over previous
#include <cuda_runtime.h>
#include <stdint.h>

// carry_save_adder: exact-binary reduction.
// S_b = sum over kept i of value(x[b,i,:]); out bits = S_b & 0xFFFF, carry = S_b >> 16.
// Non-persistent, in-order CTAs for compact DRAM footprint: each CTA owns 16
// consecutive rows (64KB); warp w handles rows w and w+8. FFMA-imm nibble
// accumulation, loop-invariant weight 2^((lane&3)*4), exact fp32 (S < 2^22).

__global__ void __launch_bounds__(256, 8)
csa_kernel(const float4* __restrict__ x, const int* __restrict__ mask,
           float* __restrict__ out, int B)
{
    const unsigned FULL = 0xFFFFFFFFu;
    const int lane = threadIdx.x & 31;
    const int wib  = threadIdx.x >> 5;              // 0..7
    const int base = (blockIdx.x << 4) + wib;       // first row for this warp

    // Keep mask over the 64 values (indices 0,1 always kept).
    const unsigned mb_lo = __ballot_sync(FULL, mask[lane]      > 0) | 3u;
    const unsigned mb_hi = __ballot_sync(FULL, mask[lane + 32] > 0);

    // Chunk t of this lane holds value index i = 8t + (lane>>2).
    const unsigned q = (unsigned)lane >> 2;
    float keepf[8];
    #pragma unroll
    for (int t = 0; t < 8; ++t) {
        unsigned bit = (t < 4) ? ((mb_lo >> (8 * t + q)) & 1u)
                               : ((mb_hi >> (8 * (t - 4) + q)) & 1u);
        keepf[t] = bit ? 1.0f : 0.0f;
    }
    // Loop-invariant nibble weight 2^((lane&3)*4).
    const float wgt = __int_as_float((127 + (((int)lane & 3) << 2)) << 23);

    #pragma unroll
    for (int rr = 0; rr < 2; ++rr) {
        const int row = base + (rr << 3);           // base, base+8
        if (row >= B) break;
        const float4* r = x + (size_t)row * 256;

        float sumf = 0.0f;
        #pragma unroll
        for (int t = 0; t < 8; ++t) {
            float4 v = __ldcs(&r[lane + (t << 5)]);
            float part = v.x;
            part = fmaf(v.y, 2.0f, part);
            part = fmaf(v.z, 4.0f, part);
            part = fmaf(v.w, 8.0f, part);
            sumf = fmaf(part, keepf[t], sumf);
        }
        sumf *= wgt;

        // Warp reduction (exact: integer-valued floats, total < 2^22).
        #pragma unroll
        for (int off = 16; off; off >>= 1)
            sumf += __shfl_xor_sync(FULL, sumf, off);

        const unsigned s = (unsigned)sumf;
        if (lane < 16)
            out[(size_t)row * 16 + lane] = (float)((s >> lane) & 1u);
        else if (lane == 16)
            out[(size_t)B * 16 + row] = (float)(s >> 16);
    }
}

extern "C" void kernel_launch(void* const* d_in, const int* in_sizes, int n_in,
                              void* d_out, int out_size)
{
    const float4* x   = (const float4*)d_in[0];   // (B, 64, 16) float32
    const int*    msk = (const int*)d_in[1];      // (64,) int32
    float*        out = (float*)d_out;            // B*16 output bits, then B carries

    int B = in_sizes[0] / 1024;                   // 64*16 floats per batch row

    int blocks = (B + 15) / 16;                   // 16 rows (64KB) per CTA
    csa_kernel<<<blocks, 256>>>(x, msk, out, B);
}

// round 7
// speedup vs baseline: 1.0920x; 1.0013x over previous
#include <cuda_runtime.h>
#include <stdint.h>

// carry_save_adder: exact-binary reduction.
// S_b = sum over kept i of value(x[b,i,:]); out bits = S_b & 0xFFFF, carry = S_b >> 16.
// R2 structure (best measured: non-persistent in-order CTAs, 1 row/warp) with
// L2::256B fetch-granularity hints on the loads: each LDG.128 triggers a 256B
// L2 fill, halving DRAM-side request count for the read-once stream.

__device__ __forceinline__ float4 ldg_nc_256B(const float4* p) {
    float4 v;
    asm("ld.global.nc.L2::256B.v4.f32 {%0,%1,%2,%3}, [%4];"
        : "=f"(v.x), "=f"(v.y), "=f"(v.z), "=f"(v.w)
        : "l"(p));
    return v;
}

__global__ void __launch_bounds__(256)
csa_kernel(const float4* __restrict__ x, const int* __restrict__ mask,
           float* __restrict__ out, int B)
{
    const unsigned FULL = 0xFFFFFFFFu;
    const int lane = threadIdx.x & 31;
    const int warp = (blockIdx.x << 3) + (threadIdx.x >> 5);
    if (warp >= B) return;

    // Keep mask over the 64 values (indices 0,1 always kept).
    const unsigned mb_lo = __ballot_sync(FULL, mask[lane]      > 0) | 3u;
    const unsigned mb_hi = __ballot_sync(FULL, mask[lane + 32] > 0);

    // Chunk t of this lane holds value index i = 8t + (lane>>2); keep weight:
    const unsigned q = (unsigned)lane >> 2;
    float keepf[8];
    #pragma unroll
    for (int t = 0; t < 8; ++t) {
        unsigned bit = (t < 4) ? ((mb_lo >> (8 * t + q)) & 1u)
                               : ((mb_hi >> (8 * (t - 4) + q)) & 1u);
        keepf[t] = bit ? 1.0f : 0.0f;
    }
    // Loop-invariant nibble weight 2^((lane&3)*4).
    const float wgt = __int_as_float((127 + (((int)lane & 3) << 2)) << 23);

    const float4* row = x + (size_t)warp * 256;

    float sumf = 0.0f;
    #pragma unroll
    for (int t = 0; t < 8; ++t) {
        float4 v = ldg_nc_256B(&row[lane + (t << 5)]);
        float part = v.x;
        part = fmaf(v.y, 2.0f, part);
        part = fmaf(v.z, 4.0f, part);
        part = fmaf(v.w, 8.0f, part);
        sumf = fmaf(part, keepf[t], sumf);
    }
    sumf *= wgt;

    // Warp reduction (exact: integer-valued floats, total < 2^22).
    #pragma unroll
    for (int off = 16; off; off >>= 1)
        sumf += __shfl_xor_sync(FULL, sumf, off);

    const unsigned s = (unsigned)sumf;
    if (lane < 16)
        out[(size_t)warp * 16 + lane] = (float)((s >> lane) & 1u);
    else if (lane == 16)
        out[(size_t)B * 16 + warp] = (float)(s >> 16);
}

extern "C" void kernel_launch(void* const* d_in, const int* in_sizes, int n_in,
                              void* d_out, int out_size)
{
    const float4* x   = (const float4*)d_in[0];   // (B, 64, 16) float32
    const int*    msk = (const int*)d_in[1];      // (64,) int32
    float*        out = (float*)d_out;            // B*16 output bits, then B carries

    int B = in_sizes[0] / 1024;                   // 64*16 floats per batch row
    int blocks = (B + 7) / 8;                     // 8 rows per CTA, in launch order
    csa_kernel<<<blocks, 256>>>(x, msk, out, B);
}

// round 8
// speedup vs baseline: 1.1176x; 1.0235x over previous
#include <cuda_runtime.h>
#include <stdint.h>

// carry_save_adder: exact-binary reduction.
// S_b = sum over kept i of value(x[b,i,:]); out bits = S_b & 0xFFFF, carry = S_b >> 16.
// Non-persistent in-order CTAs (best measured structure), one warp per row.
// Loads: ld.global.nc + L2::256B fetch granularity + evict_first cache policy
// (read-once stream must not churn L2). FFMA-imm nibble math, exact fp32.

__device__ __forceinline__ float4 ldg_stream(const float4* p, unsigned long long pol) {
    float4 v;
    asm("ld.global.nc.L2::cache_hint.L2::256B.v4.f32 {%0,%1,%2,%3}, [%4], %5;"
        : "=f"(v.x), "=f"(v.y), "=f"(v.z), "=f"(v.w)
        : "l"(p), "l"(pol));
    return v;
}

__global__ void __launch_bounds__(512)
csa_kernel(const float4* __restrict__ x, const int* __restrict__ mask,
           float* __restrict__ out, int B)
{
    const unsigned FULL = 0xFFFFFFFFu;
    const int lane = threadIdx.x & 31;
    const int warp = (blockIdx.x << 4) + (threadIdx.x >> 5);
    if (warp >= B) return;

    unsigned long long pol;
    asm("createpolicy.fractional.L2::evict_first.b64 %0, 1.0;" : "=l"(pol));

    // Keep mask over the 64 values (indices 0,1 always kept).
    const unsigned mb_lo = __ballot_sync(FULL, mask[lane]      > 0) | 3u;
    const unsigned mb_hi = __ballot_sync(FULL, mask[lane + 32] > 0);

    // Chunk t of this lane holds value index i = 8t + (lane>>2); keep weight:
    const unsigned q = (unsigned)lane >> 2;
    float keepf[8];
    #pragma unroll
    for (int t = 0; t < 8; ++t) {
        unsigned bit = (t < 4) ? ((mb_lo >> (8 * t + q)) & 1u)
                               : ((mb_hi >> (8 * (t - 4) + q)) & 1u);
        keepf[t] = bit ? 1.0f : 0.0f;
    }
    // Loop-invariant nibble weight 2^((lane&3)*4).
    const float wgt = __int_as_float((127 + (((int)lane & 3) << 2)) << 23);

    const float4* row = x + (size_t)warp * 256;

    float sumf = 0.0f;
    #pragma unroll
    for (int t = 0; t < 8; ++t) {
        float4 v = ldg_stream(&row[lane + (t << 5)], pol);
        float part = v.x;
        part = fmaf(v.y, 2.0f, part);
        part = fmaf(v.z, 4.0f, part);
        part = fmaf(v.w, 8.0f, part);
        sumf = fmaf(part, keepf[t], sumf);
    }
    sumf *= wgt;

    // Warp reduction (exact: integer-valued floats, total < 2^22).
    #pragma unroll
    for (int off = 16; off; off >>= 1)
        sumf += __shfl_xor_sync(FULL, sumf, off);

    const unsigned s = (unsigned)sumf;
    if (lane < 16)
        out[(size_t)warp * 16 + lane] = (float)((s >> lane) & 1u);
    else if (lane == 16)
        out[(size_t)B * 16 + warp] = (float)(s >> 16);
}

extern "C" void kernel_launch(void* const* d_in, const int* in_sizes, int n_in,
                              void* d_out, int out_size)
{
    const float4* x   = (const float4*)d_in[0];   // (B, 64, 16) float32
    const int*    msk = (const int*)d_in[1];      // (64,) int32
    float*        out = (float*)d_out;            // B*16 output bits, then B carries

    int B = in_sizes[0] / 1024;                   // 64*16 floats per batch row
    int blocks = (B + 15) / 16;                   // 16 rows per 512-thread CTA
    csa_kernel<<<blocks, 512>>>(x, msk, out, B);
}